// round 16
// baseline (speedup 1.0000x reference)
#include <cuda_runtime.h>
#include <cstdint>

#define NMODELS 128
#define SZ      256
#define BATCH   4096
#define NT      256
#define TILE_O  32
#define NTILES  8
#define CH      8
#define HCH     4
#define NWORK   (NMODELS * NTILES)   // 1024
#define GRID    444                  // 148 SMs x 3 CTAs

#define XPITCH  260
#define X_FLOATS    (CH * XPITCH)          // 2080 per buffer
#define PART_FLOATS (CH * TILE_O * 9)      // 2304
#define SMEM_BYTES  ((2 * X_FLOATS + PART_FLOATS + 32) * 4 + BATCH * 2 + 16)

__device__ int g_work;
__device__ int g_done;

__device__ __forceinline__ uint32_t smem_u32(const void* p) {
    uint32_t a;
    asm("{ .reg .u64 t; cvta.to.shared.u64 t, %1; cvt.u32.u64 %0, t; }"
        : "=r"(a) : "l"(p));
    return a;
}
__device__ __forceinline__ void cp16(uint32_t dst, const void* src) {
    asm volatile("cp.async.cg.shared.global [%0], [%1], 16;"
                 :: "r"(dst), "l"(src));
}

__global__ void __launch_bounds__(NT, 3)
fused_kernel(const float* __restrict__ inp,
             const int*   __restrict__ ids,
             const float* __restrict__ wlut,
             const float* __restrict__ blut,
             float* __restrict__ out)
{
    extern __shared__ float smem[];
    float* x0_s   = smem;                          // [CH][XPITCH] ping
    float* x1_s   = x0_s + X_FLOATS;               // pong
    float* part   = x1_s + X_FLOATS;               // [(s*32+o)*9 + warp]
    float* bias_s = part + PART_FLOATS;            // [32]
    unsigned short* bucket = (unsigned short*)(bias_s + 32);
    __shared__ int cnt_s;
    __shared__ int w_s;

    const int t    = threadIdx.x;
    const int og   = t & 7;         // 4 outputs: og*4..+3
    const int ks   = t >> 3;        // k-slice: ks*8..+7 (0..31)
    const int lane = t & 31;
    const int warp = t >> 5;        // partial slot 0..7

    for (;;) {
        if (t == 0) w_s = atomicAdd(&g_work, 1);
        __syncthreads();            // w_s visible; bucket/part safe to reuse
        const int w = w_s;
        if (w >= NWORK) break;

        const int m    = w >> 3;
        const int tile = w & 7;

        if (t == 0) cnt_s = 0;
        __syncthreads();

        // ---- scan agent_ids (int4 loads) -> smem bucket ----
        const int4* ids4 = (const int4*)ids;
        #pragma unroll
        for (int i = 0; i < BATCH / (4 * NT); i++) {
            int c  = t + i * NT;
            int4 v = __ldg(&ids4[c]);
            int b  = c * 4;
            if (v.x == m) bucket[atomicAdd(&cnt_s, 1)] = (unsigned short)(b);
            if (v.y == m) bucket[atomicAdd(&cnt_s, 1)] = (unsigned short)(b + 1);
            if (v.z == m) bucket[atomicAdd(&cnt_s, 1)] = (unsigned short)(b + 2);
            if (v.w == m) bucket[atomicAdd(&cnt_s, 1)] = (unsigned short)(b + 3);
        }

        // ---- this thread's W block into registers (8 x float4) ----
        float4 wreg[8];
        {
            const float* wp = wlut + (size_t)m * SZ * SZ + (size_t)(ks * 8) * SZ
                              + tile * TILE_O + og * 4;
            #pragma unroll
            for (int i = 0; i < 8; i++)
                wreg[i] = __ldg((const float4*)(wp + (size_t)i * SZ));
        }

        if (t < 8)
            ((float4*)bias_s)[t] =
                __ldg(&((const float4*)(blut + m * SZ + tile * TILE_O))[t]);

        __syncthreads();
        const int cnt = cnt_s;
        if (cnt == 0) continue;

        // ---- async prefetch of chunk s0: 1 cp16 per thread x 2 rounds ----
        auto prefetch = [&](int s0, float* xbuf) {
            #pragma unroll
            for (int i = 0; i < 2; i++) {
                int k  = t + i * NT;                 // 0..511
                int s  = k >> 6;
                int i4 = k & 63;
                int idx = min(s0 + s, cnt - 1);      // clamp; extras discarded
                const float4* src = (const float4*)(inp + (size_t)bucket[idx] * SZ) + i4;
                cp16(smem_u32(&xbuf[s * XPITCH + i4 * 4]), src);
            }
            asm volatile("cp.async.commit_group;" ::: "memory");
        };

        prefetch(0, x0_s);

        for (int s0 = 0, c = 0; s0 < cnt; s0 += CH, c++) {
            float* xb = (c & 1) ? x1_s : x0_s;
            float* xn = (c & 1) ? x0_s : x1_s;

            asm volatile("cp.async.wait_group 0;" ::: "memory");
            __syncthreads();   // xb visible; orders prev final-reads vs part-writes

            if (s0 + CH < cnt) prefetch(s0 + CH, xn);   // overlap with compute

            // ---- two passes of HCH samples (same acc registers) ----
            #pragma unroll
            for (int h = 0; h < 2; h++) {
                float4 acc[HCH];
                const float* xbase = &xb[(h * HCH) * XPITCH + ks * 8];
                #pragma unroll
                for (int s = 0; s < HCH; s++) {
                    float4 x0 = *(const float4*)&xbase[s * XPITCH];
                    float4 x1 = *(const float4*)&xbase[s * XPITCH + 4];
                    float4 a;
                    a.x = x0.x * wreg[0].x; a.y = x0.x * wreg[0].y;
                    a.z = x0.x * wreg[0].z; a.w = x0.x * wreg[0].w;
                    a.x = fmaf(x0.y, wreg[1].x, a.x); a.y = fmaf(x0.y, wreg[1].y, a.y);
                    a.z = fmaf(x0.y, wreg[1].z, a.z); a.w = fmaf(x0.y, wreg[1].w, a.w);
                    a.x = fmaf(x0.z, wreg[2].x, a.x); a.y = fmaf(x0.z, wreg[2].y, a.y);
                    a.z = fmaf(x0.z, wreg[2].z, a.z); a.w = fmaf(x0.z, wreg[2].w, a.w);
                    a.x = fmaf(x0.w, wreg[3].x, a.x); a.y = fmaf(x0.w, wreg[3].y, a.y);
                    a.z = fmaf(x0.w, wreg[3].z, a.z); a.w = fmaf(x0.w, wreg[3].w, a.w);

                    a.x = fmaf(x1.x, wreg[4].x, a.x); a.y = fmaf(x1.x, wreg[4].y, a.y);
                    a.z = fmaf(x1.x, wreg[4].z, a.z); a.w = fmaf(x1.x, wreg[4].w, a.w);
                    a.x = fmaf(x1.y, wreg[5].x, a.x); a.y = fmaf(x1.y, wreg[5].y, a.y);
                    a.z = fmaf(x1.y, wreg[5].z, a.z); a.w = fmaf(x1.y, wreg[5].w, a.w);
                    a.x = fmaf(x1.z, wreg[6].x, a.x); a.y = fmaf(x1.z, wreg[6].y, a.y);
                    a.z = fmaf(x1.z, wreg[6].z, a.z); a.w = fmaf(x1.z, wreg[6].w, a.w);
                    a.x = fmaf(x1.w, wreg[7].x, a.x); a.y = fmaf(x1.w, wreg[7].y, a.y);
                    a.z = fmaf(x1.w, wreg[7].z, a.z); a.w = fmaf(x1.w, wreg[7].w, a.w);
                    acc[s] = a;
                }

                // ---- reduce: 2 shfl stages (4 k-slices/warp), 8 warp partials ----
                #pragma unroll
                for (int s = 0; s < HCH; s++) {
                    float vx = acc[s].x, vy = acc[s].y, vz = acc[s].z, vw = acc[s].w;
                    vx += __shfl_down_sync(0xffffffffu, vx, 8);
                    vy += __shfl_down_sync(0xffffffffu, vy, 8);
                    vz += __shfl_down_sync(0xffffffffu, vz, 8);
                    vw += __shfl_down_sync(0xffffffffu, vw, 8);
                    vx += __shfl_down_sync(0xffffffffu, vx, 16);
                    vy += __shfl_down_sync(0xffffffffu, vy, 16);
                    vz += __shfl_down_sync(0xffffffffu, vz, 16);
                    vw += __shfl_down_sync(0xffffffffu, vw, 16);
                    if (lane < 8) {
                        int o  = og * 4;
                        int sp = h * HCH + s;
                        part[(sp * TILE_O + o + 0) * 9 + warp] = vx;
                        part[(sp * TILE_O + o + 1) * 9 + warp] = vy;
                        part[(sp * TILE_O + o + 2) * 9 + warp] = vz;
                        part[(sp * TILE_O + o + 3) * 9 + warp] = vw;
                    }
                }
            }
            __syncthreads();

            // ---- final: exactly 1 output per thread (CH*32 == NT) ----
            {
                int s = t >> 5;               // 0..7
                int o = t & 31;
                if (s0 + s < cnt) {
                    const float* pp = &part[(s * TILE_O + o) * 9];
                    float sum = bias_s[o];
                    #pragma unroll
                    for (int g = 0; g < 8; g++) sum += pp[g];
                    out[(size_t)bucket[s0 + s] * SZ + tile * TILE_O + o] = sum;
                }
            }
            // no trailing barrier: next iteration's top sync orders part reuse
        }
    }

    // ---- self-resetting work counters (graph-replay safe) ----
    __syncthreads();
    if (t == 0) {
        if (atomicAdd(&g_done, 1) == GRID - 1) {
            g_work = 0;
            g_done = 0;
        }
    }
}

extern "C" void kernel_launch(void* const* d_in, const int* in_sizes, int n_in,
                              void* d_out, int out_size) {
    const float* inp  = (const float*)d_in[0];
    const int*   ids  = (const int*)  d_in[1];
    const float* wlut = (const float*)d_in[2];
    const float* blut = (const float*)d_in[3];
    float* out = (float*)d_out;

    cudaFuncSetAttribute(fused_kernel,
                         cudaFuncAttributeMaxDynamicSharedMemorySize, SMEM_BYTES);

    fused_kernel<<<GRID, NT, SMEM_BYTES>>>(inp, ids, wlut, blut, out);
}

// round 17
// speedup vs baseline: 1.0504x; 1.0504x over previous
#include <cuda_runtime.h>
#include <cstdint>

#define NMODELS 128
#define SZ      256
#define BATCH   4096
#define NT      256
#define TILE_O  64
#define CH      16

// smem layout (bytes)
#define OFF_WHI    0                       // [256 k][64 n] bf16, swizzled rows (128B)
#define OFF_WLO    32768
#define OFF_X      65536                   // 4 buffers: (buf*2 + hilo)*XBUF
#define XPB        528                     // bytes per staged sample row (256 bf16 + pad)
#define XBUF       8448                    // 16 rows * 528
#define OFF_BIAS   (OFF_X + 4 * XBUF)      // 99328
#define OFF_BUCKET (OFF_BIAS + 256)        // 99584
#define SMEM_BYTES (OFF_BUCKET + BATCH * 2)  // 107776 -> 2 CTAs/SM

__device__ __forceinline__ uint32_t smem_u32(const void* p) {
    uint32_t a;
    asm("{ .reg .u64 t; cvta.to.shared.u64 t, %1; cvt.u32.u64 %0, t; }"
        : "=r"(a) : "l"(p));
    return a;
}
// pack two fp32 into bf16x2 (x0 -> low half)
__device__ __forceinline__ uint32_t packhi(float x0, float x1) {
    uint32_t h;
    asm("cvt.rn.bf16x2.f32 %0, %1, %2;" : "=r"(h) : "f"(x1), "f"(x0));
    return h;
}
__device__ __forceinline__ uint32_t packlo(float x0, float x1, uint32_t h) {
    float h0 = __uint_as_float(h << 16);
    float h1 = __uint_as_float(h & 0xffff0000u);
    float r0 = x0 - h0, r1 = x1 - h1;
    uint32_t l;
    asm("cvt.rn.bf16x2.f32 %0, %1, %2;" : "=r"(l) : "f"(r1), "f"(r0));
    return l;
}
__device__ __forceinline__ void ldmA(uint32_t addr, uint32_t* a) {
    asm volatile("ldmatrix.sync.aligned.m8n8.x4.shared.b16 {%0,%1,%2,%3}, [%4];"
                 : "=r"(a[0]), "=r"(a[1]), "=r"(a[2]), "=r"(a[3]) : "r"(addr));
}
__device__ __forceinline__ void ldmB(uint32_t addr, uint32_t* b) {
    asm volatile("ldmatrix.sync.aligned.m8n8.x2.trans.shared.b16 {%0,%1}, [%2];"
                 : "=r"(b[0]), "=r"(b[1]) : "r"(addr));
}
__device__ __forceinline__ void mma16816(float* d, const uint32_t* a, const uint32_t* b) {
    asm volatile("mma.sync.aligned.m16n8k16.row.col.f32.bf16.bf16.f32 "
                 "{%0,%1,%2,%3}, {%4,%5,%6,%7}, {%8,%9}, {%0,%1,%2,%3};"
                 : "+f"(d[0]), "+f"(d[1]), "+f"(d[2]), "+f"(d[3])
                 : "r"(a[0]), "r"(a[1]), "r"(a[2]), "r"(a[3]),
                   "r"(b[0]), "r"(b[1]));
}

__global__ void __launch_bounds__(NT, 2)
fused_kernel(const float* __restrict__ inp,
             const int*   __restrict__ ids,
             const float* __restrict__ wlut,
             const float* __restrict__ blut,
             float* __restrict__ out)
{
    extern __shared__ char smem[];
    unsigned short* bucket = (unsigned short*)(smem + OFF_BUCKET);
    float* bias_s = (float*)(smem + OFF_BIAS);
    __shared__ int cnt_s;
    const uint32_t smb = smem_u32(smem);

    const int t    = threadIdx.x;
    const int lane = t & 31;
    const int w    = t >> 5;            // warp 0..7 -> n-block w*8
    const int m    = blockIdx.x >> 2;
    const int tile = blockIdx.x & 3;

    if (t == 0) cnt_s = 0;
    __syncthreads();

    // ---- scan agent_ids (int4) -> smem bucket ----
    const int4* ids4 = (const int4*)ids;
    #pragma unroll
    for (int i = 0; i < BATCH / (4 * NT); i++) {
        int c  = t + i * NT;
        int4 v = __ldg(&ids4[c]);
        int b  = c * 4;
        if (v.x == m) bucket[atomicAdd(&cnt_s, 1)] = (unsigned short)(b);
        if (v.y == m) bucket[atomicAdd(&cnt_s, 1)] = (unsigned short)(b + 1);
        if (v.z == m) bucket[atomicAdd(&cnt_s, 1)] = (unsigned short)(b + 2);
        if (v.w == m) bucket[atomicAdd(&cnt_s, 1)] = (unsigned short)(b + 3);
    }

    // ---- stage W tile -> smem bf16 hi/lo, [k][n] 128B rows, 16B XOR swizzle ----
    {
        const float* wbase = wlut + (size_t)m * SZ * SZ + tile * TILE_O;
        #pragma unroll
        for (int i = 0; i < 16; i++) {
            int f = t + i * NT;           // coalesced float4 index over [256][16]
            int j = f & 15;               // float4 within 64-col row
            int k = f >> 4;               // k row
            float4 v = __ldg((const float4*)(wbase + (size_t)k * SZ) + j);
            uint32_t h0 = packhi(v.x, v.y), h1 = packhi(v.z, v.w);
            uint32_t l0 = packlo(v.x, v.y, h0), l1 = packlo(v.z, v.w, h1);
            uint32_t off = (uint32_t)(k * 128 + ((((j >> 1) ^ (k & 7))) << 4)
                                      + ((j & 1) << 3));
            *(uint2*)(smem + OFF_WHI + off) = make_uint2(h0, h1);
            *(uint2*)(smem + OFF_WLO + off) = make_uint2(l0, l1);
        }
    }
    if (t < 16)
        ((float4*)bias_s)[t] = __ldg(&((const float4*)(blut + m * SZ + tile * TILE_O))[t]);

    __syncthreads();
    const int cnt = cnt_s;
    if (cnt == 0) return;

    // ---- x staging helpers: thread owns (row s = t>>4, 16-k quarter q = t&15) ----
    const int sr = t >> 4;
    const int sq = t & 15;

    auto stageLDG = [&](int s0, float4* r) {
        int idx = min(s0 + sr, cnt - 1);
        const float4* src = (const float4*)(inp + (size_t)bucket[idx] * SZ) + sq * 4;
        r[0] = __ldg(src);     r[1] = __ldg(src + 1);
        r[2] = __ldg(src + 2); r[3] = __ldg(src + 3);
    };
    auto stageSTS = [&](int b, const float4* r) {
        char* hb = smem + OFF_X + (b * 2) * XBUF + sr * XPB + sq * 32;
        uint32_t h[8], l[8];
        #pragma unroll
        for (int p = 0; p < 4; p++) {
            h[2 * p]     = packhi(r[p].x, r[p].y);
            h[2 * p + 1] = packhi(r[p].z, r[p].w);
            l[2 * p]     = packlo(r[p].x, r[p].y, h[2 * p]);
            l[2 * p + 1] = packlo(r[p].z, r[p].w, h[2 * p + 1]);
        }
        *(uint4*)(hb)              = make_uint4(h[0], h[1], h[2], h[3]);
        *(uint4*)(hb + 16)         = make_uint4(h[4], h[5], h[6], h[7]);
        *(uint4*)(hb + XBUF)       = make_uint4(l[0], l[1], l[2], l[3]);
        *(uint4*)(hb + XBUF + 16)  = make_uint4(l[4], l[5], l[6], l[7]);
    };

    // ---- per-lane constants for ldmatrix / epilogue ----
    const int ar   = lane & 15;            // A row
    const int akof = (lane >> 4) << 3;     // A k offset (0 or 8)
    const int er   = lane >> 2;            // epilogue row in frag
    const int ec   = (lane & 3) << 1;      // epilogue col pair
    const int col  = tile * TILE_O + w * 8 + ec;
    const float bb0 = bias_s[w * 8 + ec];
    const float bb1 = bias_s[w * 8 + ec + 1];

    const int nch = (cnt + CH - 1) / CH;
    float4 xr[4];
    stageLDG(0, xr);
    stageSTS(0, xr);
    __syncthreads();

    for (int c = 0; c < nch; c++) {
        if (c + 1 < nch) stageLDG((c + 1) * CH, xr);

        float d[4] = {0.f, 0.f, 0.f, 0.f};
        const uint32_t xb = smb + OFF_X + (uint32_t)((c & 1) * 2 * XBUF);

        #pragma unroll
        for (int kk = 0; kk < 16; kk++) {
            const int k0 = kk * 16;
            uint32_t ah[4], al[4], bh[2], bl[2];
            uint32_t aoff = xb + (uint32_t)(ar * XPB + (k0 + akof) * 2);
            ldmA(aoff, ah);
            ldmA(aoff + XBUF, al);
            int kb = k0 + ar;
            uint32_t boff = smb + OFF_WHI
                          + (uint32_t)(kb * 128 + ((w ^ (kb & 7)) << 4));
            ldmB(boff, bh);
            ldmB(boff + 32768, bl);
            mma16816(d, ah, bh);
            mma16816(d, al, bh);
            mma16816(d, ah, bl);
        }

        // ---- epilogue: frag rows er, er+8 -> gathered output rows ----
        const int s0 = c * CH;
        if (s0 + er < cnt) {
            float2 v = make_float2(d[0] + bb0, d[1] + bb1);
            *(float2*)(out + (size_t)bucket[s0 + er] * SZ + col) = v;
        }
        if (s0 + er + 8 < cnt) {
            float2 v = make_float2(d[2] + bb0, d[3] + bb1);
            *(float2*)(out + (size_t)bucket[s0 + er + 8] * SZ + col) = v;
        }

        if (c + 1 < nch) stageSTS((c + 1) & 1, xr);
        __syncthreads();
    }
}

extern "C" void kernel_launch(void* const* d_in, const int* in_sizes, int n_in,
                              void* d_out, int out_size) {
    const float* inp  = (const float*)d_in[0];
    const int*   ids  = (const int*)  d_in[1];
    const float* wlut = (const float*)d_in[2];
    const float* blut = (const float*)d_in[3];
    float* out = (float*)d_out;

    cudaFuncSetAttribute(fused_kernel,
                         cudaFuncAttributeMaxDynamicSharedMemorySize, SMEM_BYTES);

    fused_kernel<<<NMODELS * 4, NT, SMEM_BYTES>>>(inp, ids, wlut, blut, out);
}